// round 6
// baseline (speedup 1.0000x reference)
#include <cuda_runtime.h>
#include <cuda_bf16.h>

// P1 FEM evaluation on a structured 17x17 grid over [0,1]^2.
// Direct cell lookup replaces the reference's 512-triangle scan.
//
// Bitwise-faithful decision logic vs the JAX reference (validated R4/R5,
// rel_err 3.76e-8):
//  - Minv entries are exactly {+-16, 0}; x*16 is an exact exponent shift,
//    so (ux - floor(ux)) == 16*fl(X - xs[i]) bit-exactly.
//  - TOL = 1e-10 is below fp32 ulp on interior grid lines -> those points
//    fail every strict bbox test in the reference -> output 0 (`dead`).
//    x==0 / y==0 edges survive (bbox lower bound -1e-10 is representable).
//  - scan order = lower triangles then upper -> upper wins on the diagonal.
//
// R6 changes (latency/tail-bound profile; no pipe >45%):
//  - 32-way bank-replicated weight table: ws[idx*32 + lane] -> every LDS.32
//    is conflict-free (4 wavefronts/point vs ~8-12 with random gather)
//  - exactly 888 = 148 SMs x 6 resident blocks -> single full wave,
//    grid-stride loop removes the 136-block straggler tail
//  - __launch_bounds__(256, 6) pins regs so 6 blocks/SM actually fit

static constexpr float TOLF   = 1e-10f;
static constexpr int   N_OUT4 = (8 * 262144) / 4;   // 524,288 float4 outputs
static constexpr int   BLOCKS = 148 * 6;             // 888: one full wave
static constexpr int   THREADS = 256;

__device__ __forceinline__ float eval_point(float X, float Y,
                                            const float* __restrict__ ws,
                                            int lane) {
    float ux = X * 16.0f;              // exact (power-of-2 scale)
    float uy = Y * 16.0f;
    float fx = floorf(ux);
    float fy = floorf(uy);
    // Interior grid line -> reference's strict bbox test fails everywhere.
    bool dead = ((ux == fx) && (fx != 0.0f)) || ((uy == fy) && (fy != 0.0f));
    fx = fminf(fx, 15.0f);
    fy = fminf(fy, 15.0f);
    int i = (int)fx;
    int j = (int)fy;

    float dx16 = ux - fx;              // == 16 * fl(X - xs[i]) exactly
    float dy16 = uy - fy;              // == 16 * fl(Y - xs[j]) exactly

    // Lower triangle (v00, v10, v11):  s=(dx-dy)*16, t=dy*16
    float sl = dx16 - dy16;
    float tl = dy16;
    // Upper triangle (v00, v11, v01):  s=dx*16, t=(dy-dx)*16
    float su = dx16;
    float tu = dy16 - dx16;

    // Bank-replicated table: copy per lane -> conflict-free LDS.32.
    int base = (i * 17 + j) * 32 + lane;        // vid = i*17 + j
    float w00 = ws[base];                        // (i  , j  )
    float w01 = ws[base + 1 * 32];               // (i  , j+1)
    float w10 = ws[base + 17 * 32];              // (i+1, j  )
    float w11 = ws[base + 18 * 32];              // (i+1, j+1)

    float val = 0.0f;
    if ((sl > -TOLF) && (tl > -TOLF) && ((sl + tl) < 1.0f))
        val = (1.0f - sl - tl) * w00 + sl * w10 + tl * w11;
    if ((su > -TOLF) && (tu > -TOLF) && ((su + tu) < 1.0f))
        val = (1.0f - su - tu) * w00 + su * w11 + tu * w01;  // upper overrides
    return dead ? 0.0f : val;
}

__global__ void __launch_bounds__(THREADS, 6)
p1_eval_kernel(const float4* __restrict__ x4,
               const float*  __restrict__ w,
               float4*       __restrict__ out4) {
    // 32 bank-aligned copies of the 289-entry weight table (36,992 B).
    __shared__ float ws[289 * 32];
    for (int t = threadIdx.x; t < 289 * 32; t += THREADS)
        ws[t] = w[t >> 5];             // copy index = t & 31, value idx = t >> 5
    __syncthreads();

    const int lane = threadIdx.x & 31;
    const int stride = BLOCKS * THREADS;

    // Grid-stride over output float4s (4 points = 2 input float4 each).
    for (int o = blockIdx.x * THREADS + threadIdx.x; o < N_OUT4; o += stride) {
        float4 a0 = x4[2 * o];
        float4 a1 = x4[2 * o + 1];
        float4 r;
        r.x = eval_point(a0.x, a0.y, ws, lane);
        r.y = eval_point(a0.z, a0.w, ws, lane);
        r.z = eval_point(a1.x, a1.y, ws, lane);
        r.w = eval_point(a1.z, a1.w, ws, lane);
        out4[o] = r;
    }
}

extern "C" void kernel_launch(void* const* d_in, const int* in_sizes, int n_in,
                              void* d_out, int out_size) {
    // Identify inputs by element count: x = largest (4,194,304 floats),
    // weight = 289 floats.
    const float* x = nullptr;
    const float* w = nullptr;
    int max_sz = -1;
    for (int k = 0; k < n_in; k++) {
        if (in_sizes[k] == 289) w = (const float*)d_in[k];
        if (in_sizes[k] > max_sz) { max_sz = in_sizes[k]; x = (const float*)d_in[k]; }
    }

    p1_eval_kernel<<<BLOCKS, THREADS>>>((const float4*)x, w, (float4*)d_out);
}

// round 7
// speedup vs baseline: 1.0439x; 1.0439x over previous
#include <cuda_runtime.h>
#include <cuda_bf16.h>

// P1 FEM evaluation on a structured 17x17 grid over [0,1]^2.
// Direct cell lookup replaces the reference's 512-triangle scan.
//
// Bitwise-faithful decision logic vs the JAX reference (validated R4-R6,
// rel_err 3.76e-8):
//  - Minv entries are exactly {+-16, 0}; x*16 is an exact exponent shift,
//    so (ux - floor(ux)) == 16*fl(X - xs[i]) bit-exactly.
//  - TOL = 1e-10 is below fp32 ulp on interior grid lines -> those points
//    fail every strict bbox test in the reference -> output 0 (`dead`).
//    x==0 / y==0 edges survive (bbox lower bound -1e-10 is representable).
//  - scan order = lower triangles then upper -> upper wins on the diagonal.
//
// R7 changes (plateau diagnosis: LDS wavefronts + eval-phase latency):
//  - per-CELL packed float4 weight table (256 entries, 4 KB):
//    one LDS.128 per point instead of 4x LDS.32 (~6.5 vs ~14 wavefronts),
//    one scoreboard dependency instead of four
//  - table fill is a single iteration (256 threads <-> 256 cells),
//    unlike R6's 37-iteration replicated fill that cancelled its win
//  - cell index via exact FFMA(fx,16,fy) -> single F2I

static constexpr float TOLF = 1e-10f;

__device__ __forceinline__ float eval_point(float X, float Y,
                                            const float4* __restrict__ wq) {
    float ux = X * 16.0f;              // exact (power-of-2 scale)
    float uy = Y * 16.0f;
    float fx = floorf(ux);
    float fy = floorf(uy);
    // Interior grid line -> reference's strict bbox test fails everywhere.
    bool dead = ((ux == fx) && (fx != 0.0f)) || ((uy == fy) && (fy != 0.0f));
    fx = fminf(fx, 15.0f);
    fy = fminf(fy, 15.0f);

    float dx16 = ux - fx;              // == 16 * fl(X - xs[i]) exactly
    float dy16 = uy - fy;              // == 16 * fl(Y - xs[j]) exactly

    // cell = i*16 + j, computed exactly in fp32 (integers <= 255)
    int cell = (int)fmaf(fx, 16.0f, fy);
    float4 q = wq[cell];               // (w00, w01, w10, w11) - one LDS.128
    float w00 = q.x, w01 = q.y, w10 = q.z, w11 = q.w;

    // Lower triangle (v00, v10, v11):  s=(dx-dy)*16, t=dy*16
    float sl = dx16 - dy16;
    float tl = dy16;
    // Upper triangle (v00, v11, v01):  s=dx*16, t=(dy-dx)*16
    float su = dx16;
    float tu = dy16 - dx16;

    float val = 0.0f;
    if ((sl > -TOLF) && (tl > -TOLF) && ((sl + tl) < 1.0f))
        val = (1.0f - sl - tl) * w00 + sl * w10 + tl * w11;
    if ((su > -TOLF) && (tu > -TOLF) && ((su + tu) < 1.0f))
        val = (1.0f - su - tu) * w00 + su * w11 + tu * w01;  // upper overrides
    return dead ? 0.0f : val;
}

__global__ void __launch_bounds__(256)
p1_eval_kernel(const float4* __restrict__ x4,
               const float*  __restrict__ w,
               float4*       __restrict__ out4) {
    // Packed per-cell weight table: wq[i*16+j] = (w00, w01, w10, w11).
    __shared__ float4 wq[256];
    {
        int t = threadIdx.x;           // t = i*16 + j, i,j in [0,16)
        int i = t >> 4;
        int j = t & 15;
        int v = i * 17 + j;
        wq[t] = make_float4(w[v], w[v + 1], w[v + 17], w[v + 18]);
    }
    __syncthreads();

    // Each thread: 8 points = 4 input float4 (front-batched), 2 output float4.
    int o0 = blockIdx.x * 512 + threadIdx.x;   // output float4 index
    int o1 = o0 + 256;

    float4 a0 = x4[2 * o0];
    float4 a1 = x4[2 * o0 + 1];
    float4 b0 = x4[2 * o1];
    float4 b1 = x4[2 * o1 + 1];

    float4 r0, r1;
    r0.x = eval_point(a0.x, a0.y, wq);
    r0.y = eval_point(a0.z, a0.w, wq);
    r0.z = eval_point(a1.x, a1.y, wq);
    r0.w = eval_point(a1.z, a1.w, wq);
    r1.x = eval_point(b0.x, b0.y, wq);
    r1.y = eval_point(b0.z, b0.w, wq);
    r1.z = eval_point(b1.x, b1.y, wq);
    r1.w = eval_point(b1.z, b1.w, wq);

    out4[o0] = r0;
    out4[o1] = r1;
}

extern "C" void kernel_launch(void* const* d_in, const int* in_sizes, int n_in,
                              void* d_out, int out_size) {
    // Identify inputs by element count: x = largest (4,194,304 floats),
    // weight = 289 floats.
    const float* x = nullptr;
    const float* w = nullptr;
    int max_sz = -1;
    for (int k = 0; k < n_in; k++) {
        if (in_sizes[k] == 289) w = (const float*)d_in[k];
        if (in_sizes[k] > max_sz) { max_sz = in_sizes[k]; x = (const float*)d_in[k]; }
    }

    // 2,097,152 points -> 524,288 output float4 -> 1024 blocks x 256 threads x 2.
    p1_eval_kernel<<<1024, 256>>>((const float4*)x, w, (float4*)d_out);
}

// round 8
// speedup vs baseline: 1.0593x; 1.0148x over previous
#include <cuda_runtime.h>
#include <cuda_bf16.h>

// P1 FEM evaluation on a structured 17x17 grid over [0,1]^2.
// Direct cell lookup replaces the reference's 512-triangle scan.
//
// Bitwise-faithful decision logic vs the JAX reference (validated R4-R7,
// rel_err 3.76e-8):
//  - x*16 is an exact exponent shift; dx16 = ux - floor(ux) and
//    dy16 = uy - floor(uy) are EXACT (multiples of 2^-20 or finer),
//    and so are dx16-dy16 and the reference's s+t sums.
//  - Hence the reference's 6 triangle conditions collapse exactly:
//      lower: tl>=0 always, sl+tl = dx16 < 1 always
//      upper: su>=0 always, su+tu = dy16 < 1 always
//      -> single test: up = (dy16 - dx16) > -TOL  (upper overrides lower
//         on the shared diagonal / sub-TOL tie band, matching scan order)
//  - TOL = 1e-10 is below fp32 ulp on interior grid lines -> those points
//    fail every strict bbox test in the reference -> output 0 (`dead`).
//    x==0 / y==0 edges survive (bbox lower bound -1e-10 is representable).
//
// R8 changes (plateau = issue-slot x latency bound, L2-resident working set):
//  - branchless eval: 1 compare + 4 FSEL instead of 6 predicate chains,
//    ~10 fewer instructions per point (~40% of the thread's instr stream)
//  - dropped redundant clamps (uniform [0,1) input -> floor(ux) <= 15)
//  - keeps R7 per-cell float4 table (1x LDS.128/point, 1-iteration fill),
//    front-batched LDG.128, 1024 x 256 single wave

static constexpr float TOLF = 1e-10f;

__device__ __forceinline__ float eval_point(float X, float Y,
                                            const float4* __restrict__ wq) {
    float ux = X * 16.0f;              // exact (power-of-2 scale)
    float uy = Y * 16.0f;
    float fx = floorf(ux);
    float fy = floorf(uy);
    // Interior grid line -> reference's strict bbox test fails everywhere.
    bool dead = ((ux == fx) && (fx != 0.0f)) || ((uy == fy) && (fy != 0.0f));

    float dx = ux - fx;                // exact; == 16 * fl(X - xs[i])
    float dy = uy - fy;                // exact

    int cell = (int)fmaf(fx, 16.0f, fy);   // i*16 + j, exact in fp32
    float4 q = wq[cell];               // (w00, w01, w10, w11) - one LDS.128

    // Upper triangle wins iff dy - dx > -TOL (exact difference).
    bool up = (dy - dx) > -TOLF;

    // Shared form: val = (1 - s - t)*w00 + s*wa + t*wb
    float s  = up ? dx        : (dx - dy);
    float t  = up ? (dy - dx) : dy;
    float wa = up ? q.w : q.z;         // upper: w11 ; lower: w10
    float wb = up ? q.y : q.w;         // upper: w01 ; lower: w11
    float val = (1.0f - s - t) * q.x + s * wa + t * wb;

    return dead ? 0.0f : val;
}

__global__ void __launch_bounds__(256)
p1_eval_kernel(const float4* __restrict__ x4,
               const float*  __restrict__ w,
               float4*       __restrict__ out4) {
    // Packed per-cell weight table: wq[i*16+j] = (w00, w01, w10, w11).
    __shared__ float4 wq[256];
    {
        int t = threadIdx.x;           // t = i*16 + j, i,j in [0,16)
        int v = (t >> 4) * 17 + (t & 15);
        wq[t] = make_float4(w[v], w[v + 1], w[v + 17], w[v + 18]);
    }
    __syncthreads();

    // Each thread: 8 points = 4 input float4 (front-batched), 2 output float4.
    int o0 = blockIdx.x * 512 + threadIdx.x;   // output float4 index
    int o1 = o0 + 256;

    float4 a0 = x4[2 * o0];
    float4 a1 = x4[2 * o0 + 1];
    float4 b0 = x4[2 * o1];
    float4 b1 = x4[2 * o1 + 1];

    float4 r0, r1;
    r0.x = eval_point(a0.x, a0.y, wq);
    r0.y = eval_point(a0.z, a0.w, wq);
    r0.z = eval_point(a1.x, a1.y, wq);
    r0.w = eval_point(a1.z, a1.w, wq);
    r1.x = eval_point(b0.x, b0.y, wq);
    r1.y = eval_point(b0.z, b0.w, wq);
    r1.z = eval_point(b1.x, b1.y, wq);
    r1.w = eval_point(b1.z, b1.w, wq);

    out4[o0] = r0;
    out4[o1] = r1;
}

extern "C" void kernel_launch(void* const* d_in, const int* in_sizes, int n_in,
                              void* d_out, int out_size) {
    // Identify inputs by element count: x = largest (4,194,304 floats),
    // weight = 289 floats.
    const float* x = nullptr;
    const float* w = nullptr;
    int max_sz = -1;
    for (int k = 0; k < n_in; k++) {
        if (in_sizes[k] == 289) w = (const float*)d_in[k];
        if (in_sizes[k] > max_sz) { max_sz = in_sizes[k]; x = (const float*)d_in[k]; }
    }

    // 2,097,152 points -> 524,288 output float4 -> 1024 blocks x 256 threads x 2.
    p1_eval_kernel<<<1024, 256>>>((const float4*)x, w, (float4*)d_out);
}

// round 9
// speedup vs baseline: 1.0917x; 1.0306x over previous
#include <cuda_runtime.h>
#include <cuda_bf16.h>

// P1 FEM evaluation on a structured 17x17 grid over [0,1]^2.
// Direct cell lookup replaces the reference's 512-triangle scan.
//
// Bitwise-faithful decision logic vs the JAX reference (validated R4-R8,
// rel_err 3.76e-8):
//  - x*16 is an exact exponent shift; dx = ux - floor(ux) and
//    dy = uy - floor(uy) are EXACT, as are dx-dy and the reference s+t sums.
//  - The reference's 6 triangle conditions collapse exactly to one test:
//      up = (dy - dx) > -TOL   (upper overrides lower on the shared
//      diagonal / sub-TOL tie band, matching the scan order)
//  - TOL = 1e-10 is below fp32 ulp on interior grid lines -> those points
//    fail every strict bbox test in the reference -> output 0 (`dead`).
//    x==0 / y==0 edges survive (bbox lower bound -1e-10 is representable).
//
// R9 change (occupancy-model bug found): regs=39 -> only 6 blocks/SM ->
// 888 resident < 1024 grid -> 136-block second wave (~+1.3us tail).
//  - __launch_bounds__(256, 7) caps regs at 36 (R7 compiled at 36 naturally)
//    -> 7 blocks/SM -> capacity 1036 >= 1024 -> single full wave, no tail
//  - loads interleaved in pairs to shorten live ranges (help the 36-reg budget)

static constexpr float TOLF = 1e-10f;

__device__ __forceinline__ float eval_point(float X, float Y,
                                            const float4* __restrict__ wq) {
    float ux = X * 16.0f;              // exact (power-of-2 scale)
    float uy = Y * 16.0f;
    float fx = floorf(ux);
    float fy = floorf(uy);
    // Interior grid line -> reference's strict bbox test fails everywhere.
    bool dead = ((ux == fx) && (fx != 0.0f)) || ((uy == fy) && (fy != 0.0f));

    float dx = ux - fx;                // exact; == 16 * fl(X - xs[i])
    float dy = uy - fy;                // exact

    int cell = (int)fmaf(fx, 16.0f, fy);   // i*16 + j, exact in fp32
    float4 q = wq[cell];               // (w00, w01, w10, w11) - one LDS.128

    // Upper triangle wins iff dy - dx > -TOL (exact difference).
    bool up = (dy - dx) > -TOLF;

    // Shared form: val = (1 - s - t)*w00 + s*wa + t*wb
    float s  = up ? dx        : (dx - dy);
    float t  = up ? (dy - dx) : dy;
    float wa = up ? q.w : q.z;         // upper: w11 ; lower: w10
    float wb = up ? q.y : q.w;         // upper: w01 ; lower: w11
    float val = (1.0f - s - t) * q.x + s * wa + t * wb;

    return dead ? 0.0f : val;
}

__global__ void __launch_bounds__(256, 7)
p1_eval_kernel(const float4* __restrict__ x4,
               const float*  __restrict__ w,
               float4*       __restrict__ out4) {
    // Packed per-cell weight table: wq[i*16+j] = (w00, w01, w10, w11).
    __shared__ float4 wq[256];
    {
        int t = threadIdx.x;           // t = i*16 + j, i,j in [0,16)
        int v = (t >> 4) * 17 + (t & 15);
        wq[t] = make_float4(w[v], w[v + 1], w[v + 17], w[v + 18]);
    }
    __syncthreads();

    // Each thread: 8 points = 4 input float4, 2 output float4.
    int o0 = blockIdx.x * 512 + threadIdx.x;   // output float4 index
    int o1 = o0 + 256;

    // Pairwise-interleaved loads: enough MLP (2 LDG.128 in flight) while
    // keeping live ranges short for the 36-reg budget.
    float4 a0 = x4[2 * o0];
    float4 a1 = x4[2 * o0 + 1];
    float4 r0;
    r0.x = eval_point(a0.x, a0.y, wq);
    r0.y = eval_point(a0.z, a0.w, wq);
    r0.z = eval_point(a1.x, a1.y, wq);
    r0.w = eval_point(a1.z, a1.w, wq);
    out4[o0] = r0;

    float4 b0 = x4[2 * o1];
    float4 b1 = x4[2 * o1 + 1];
    float4 r1;
    r1.x = eval_point(b0.x, b0.y, wq);
    r1.y = eval_point(b0.z, b0.w, wq);
    r1.z = eval_point(b1.x, b1.y, wq);
    r1.w = eval_point(b1.z, b1.w, wq);
    out4[o1] = r1;
}

extern "C" void kernel_launch(void* const* d_in, const int* in_sizes, int n_in,
                              void* d_out, int out_size) {
    // Identify inputs by element count: x = largest (4,194,304 floats),
    // weight = 289 floats.
    const float* x = nullptr;
    const float* w = nullptr;
    int max_sz = -1;
    for (int k = 0; k < n_in; k++) {
        if (in_sizes[k] == 289) w = (const float*)d_in[k];
        if (in_sizes[k] > max_sz) { max_sz = in_sizes[k]; x = (const float*)d_in[k]; }
    }

    // 2,097,152 points -> 524,288 output float4 -> 1024 blocks x 256 threads x 2.
    p1_eval_kernel<<<1024, 256>>>((const float4*)x, w, (float4*)d_out);
}